// round 10
// baseline (speedup 1.0000x reference)
#include <cuda_runtime.h>
#include <cuda_bf16.h>
#include <math.h>
#include <cstdint>

#define DIMV    2048
#define SEQ     2048
#define BATCH   2
#define HEADS   16
#define DHEAD   128
#define MROWS   (BATCH*SEQ)   // 4096
#define EPSV    1e-5f

// ---------------- scratch (device globals; no allocation allowed) ----------
__device__ float g_q[(size_t)MROWS * DIMV];
__device__ float g_k[(size_t)MROWS * DIMV];
__device__ float g_attn[(size_t)MROWS * DIMV];   // reused as 2 bf16 planes of attn-out
__device__ __nv_bfloat16 g_ahi[(size_t)MROWS * DIMV];
__device__ __nv_bfloat16 g_alo[(size_t)MROWS * DIMV];
__device__ __nv_bfloat16 g_khi[(size_t)MROWS * DIMV];
__device__ __nv_bfloat16 g_klo[(size_t)MROWS * DIMV];
__device__ __nv_bfloat16 g_vhi[(size_t)MROWS * DIMV];
__device__ __nv_bfloat16 g_vlo[(size_t)MROWS * DIMV];
__device__ __nv_bfloat16 g_wqhi[(size_t)DIMV * DIMV];
__device__ __nv_bfloat16 g_wqlo[(size_t)DIMV * DIMV];
__device__ __nv_bfloat16 g_wkhi[(size_t)DIMV * DIMV];
__device__ __nv_bfloat16 g_wklo[(size_t)DIMV * DIMV];
__device__ __nv_bfloat16 g_wvhi[(size_t)DIMV * DIMV];
__device__ __nv_bfloat16 g_wvlo[(size_t)DIMV * DIMV];
__device__ __nv_bfloat16 g_wohi[(size_t)DIMV * DIMV];
__device__ __nv_bfloat16 g_wolo[(size_t)DIMV * DIMV];

// ---------------- arch-neutral tensor helpers (compute_103-safe) -----------
__device__ __forceinline__ uint32_t smem_u32(const void* p) {
    uint32_t a;
    asm("{ .reg .u64 t; cvta.to.shared.u64 t, %1; cvt.u32.u64 %0, t; }"
        : "=r"(a) : "l"(p));
    return a;
}
__device__ __forceinline__ void ldsm4(uint32_t* r, uint32_t addr) {
    asm volatile("ldmatrix.sync.aligned.m8n8.x4.shared.b16 {%0,%1,%2,%3}, [%4];"
                 : "=r"(r[0]), "=r"(r[1]), "=r"(r[2]), "=r"(r[3]) : "r"(addr));
}
__device__ __forceinline__ void ldsm4t(uint32_t* r, uint32_t addr) {
    asm volatile("ldmatrix.sync.aligned.m8n8.x4.trans.shared.b16 {%0,%1,%2,%3}, [%4];"
                 : "=r"(r[0]), "=r"(r[1]), "=r"(r[2]), "=r"(r[3]) : "r"(addr));
}
__device__ __forceinline__ void mma16816(float* c, const uint32_t* a, const uint32_t* b) {
    asm volatile("mma.sync.aligned.m16n8k16.row.col.f32.bf16.bf16.f32 "
                 "{%0,%1,%2,%3}, {%4,%5,%6,%7}, {%8,%9}, {%0,%1,%2,%3};"
                 : "+f"(c[0]), "+f"(c[1]), "+f"(c[2]), "+f"(c[3])
                 : "r"(a[0]), "r"(a[1]), "r"(a[2]), "r"(a[3]), "r"(b[0]), "r"(b[1]));
}
// pack two fp32 into bf16x2 hi + residual-lo bf16x2
__device__ __forceinline__ void psplit(float f0, float f1, uint32_t& h, uint32_t& l) {
    asm("cvt.rn.bf16x2.f32 %0, %1, %2;" : "=r"(h) : "f"(f1), "f"(f0));
    const float h0 = __uint_as_float(h << 16);
    const float h1 = __uint_as_float(h & 0xffff0000u);
    const float l0 = f0 - h0, l1 = f1 - h1;
    asm("cvt.rn.bf16x2.f32 %0, %1, %2;" : "=r"(l) : "f"(l1), "f"(l0));
}
#define CP_ASYNC16(dst, src) asm volatile("cp.async.cg.shared.global [%0], [%1], 16;" :: "r"(dst), "l"(src))
#define CP_COMMIT()          asm volatile("cp.async.commit_group;" ::: "memory")
#define CP_WAIT1()           asm volatile("cp.async.wait_group 1;" ::: "memory")
#define CP_WAIT0()           asm volatile("cp.async.wait_group 0;" ::: "memory")
// swizzled offset within a 256B-row tile (16B chunks)
__device__ __forceinline__ uint32_t SWZ(int r, int ch) {
    return (uint32_t)((r << 8) + (((ch & 7) ^ (r & 7)) << 4) + ((ch & 8) << 4));
}

// ---------------------------------------------------------------------------
// fp32 -> bf16 hi/lo split (vectorized x4)
// ---------------------------------------------------------------------------
__global__ __launch_bounds__(256)
void split_kernel(const float* __restrict__ x, __nv_bfloat16* __restrict__ hi,
                  __nv_bfloat16* __restrict__ lo, int n)
{
    int i = (blockIdx.x * blockDim.x + threadIdx.x) * 4;
    if (i >= n) return;
    float4 v = *(const float4*)(x + i);
    uint32_t h0, l0, h1, l1;
    psplit(v.x, v.y, h0, l0);
    psplit(v.z, v.w, h1, l1);
    *(uint2*)(hi + i) = make_uint2(h0, h1);
    *(uint2*)(lo + i) = make_uint2(l0, l1);
}

// ---------------------------------------------------------------------------
// bf16 3-term mma.sync GEMM (R6-verified core). Epilogue writes either fp32 C
// (+bias) or split bf16 hi/lo planes (+bias) when Chi != nullptr.
// ---------------------------------------------------------------------------
#define BUF_STRIDE 98304
#define GEMM_SMEM  (2 * BUF_STRIDE)

__global__ __launch_bounds__(256, 1)
void gemm_mma_kernel(const __nv_bfloat16* __restrict__ Ahi, const __nv_bfloat16* __restrict__ Alo,
                     const __nv_bfloat16* __restrict__ Bhi, const __nv_bfloat16* __restrict__ Blo,
                     const float* __restrict__ bias, float* __restrict__ C,
                     __nv_bfloat16* __restrict__ Chi, __nv_bfloat16* __restrict__ Clo)
{
    extern __shared__ __align__(1024) char smem[];
    const uint32_t sb = smem_u32(smem);

    const int tid  = threadIdx.x;
    const int wid  = tid >> 5;
    const int lane = tid & 31;
    const int wm   = wid >> 2;
    const int wn   = wid & 3;
    const int m0   = blockIdx.y * 128;
    const int n0   = blockIdx.x * 256;

    auto load_stage = [&](int k0, int buf) {
        const uint32_t bo = sb + buf * BUF_STRIDE;
#pragma unroll
        for (int j = 0; j < 8; j++) {
            const int c  = tid + j * 256;
            const int p  = c >> 10;
            const int r  = (c >> 3) & 127;
            const int ch = c & 7;
            const uint32_t dst = bo + p * 16384 + (r << 7) + ((ch ^ (r & 7)) << 4);
            const __nv_bfloat16* src = (p ? Alo : Ahi)
                + (size_t)(m0 + r) * DIMV + k0 + ch * 8;
            CP_ASYNC16(dst, src);
        }
#pragma unroll
        for (int j = 0; j < 16; j++) {
            const int c  = tid + j * 256;
            const int p  = c >> 11;
            const int r  = (c >> 3) & 255;
            const int ch = c & 7;
            const uint32_t dst = bo + 32768 + p * 32768 + (r << 7) + ((ch ^ (r & 7)) << 4);
            const __nv_bfloat16* src = (p ? Blo : Bhi)
                + (size_t)(n0 + r) * DIMV + k0 + ch * 8;
            CP_ASYNC16(dst, src);
        }
    };

    float acc[4][8][4];
#pragma unroll
    for (int i = 0; i < 4; i++)
#pragma unroll
        for (int j = 0; j < 8; j++)
#pragma unroll
            for (int t = 0; t < 4; t++) acc[i][j][t] = 0.f;

    const int a_row = wm * 64 + (lane & 15);
    const int a_chx = lane >> 4;
    const int b_row = wn * 64 + ((lane >> 4) << 3) + (lane & 7);
    const int b_chx = (lane >> 3) & 1;

    load_stage(0, 0);
    CP_COMMIT();

    for (int s = 0; s < 32; s++) {
        const int buf = s & 1;
        if (s + 1 < 32) { load_stage((s + 1) * 64, buf ^ 1); CP_COMMIT(); CP_WAIT1(); }
        else            { CP_WAIT0(); }
        __syncthreads();

        const uint32_t aH = sb + buf * BUF_STRIDE;
        const uint32_t aL = aH + 16384;
        const uint32_t bH = aH + 32768;
        const uint32_t bL = bH + 32768;

#pragma unroll
        for (int kk8 = 0; kk8 < 4; kk8++) {
            uint32_t ah[4][4], al[4][4], bh[8][2], bl[8][2];
            const int ach = kk8 * 2 + a_chx;
#pragma unroll
            for (int i = 0; i < 4; i++) {
                const int r = a_row + i * 16;
                const uint32_t ad = (r << 7) + ((ach ^ (r & 7)) << 4);
                ldsm4(ah[i], aH + ad);
                ldsm4(al[i], aL + ad);
            }
            const int bch = kk8 * 2 + b_chx;
#pragma unroll
            for (int jj = 0; jj < 4; jj++) {
                const int r = b_row + jj * 16;
                const uint32_t bd = (r << 7) + ((bch ^ (r & 7)) << 4);
                uint32_t t[4];
                ldsm4(t, bH + bd);
                bh[2*jj][0] = t[0];   bh[2*jj][1] = t[1];
                bh[2*jj+1][0] = t[2]; bh[2*jj+1][1] = t[3];
                ldsm4(t, bL + bd);
                bl[2*jj][0] = t[0];   bl[2*jj][1] = t[1];
                bl[2*jj+1][0] = t[2]; bl[2*jj+1][1] = t[3];
            }
#pragma unroll
            for (int i = 0; i < 4; i++)
#pragma unroll
                for (int j = 0; j < 8; j++) {
                    mma16816(acc[i][j], ah[i], bh[j]);
                    mma16816(acc[i][j], ah[i], bl[j]);
                    mma16816(acc[i][j], al[i], bh[j]);
                }
        }
        __syncthreads();
    }

    const int mw = m0 + wm * 64;
    const int nw = n0 + wn * 64;
    const int ml = lane >> 2;
    const int nl = (lane & 3) * 2;
    if (Chi == nullptr) {
#pragma unroll
        for (int j = 0; j < 8; j++) {
            const int n = nw + j * 8 + nl;
            const float b0 = bias[n], b1 = bias[n + 1];
#pragma unroll
            for (int i = 0; i < 4; i++) {
                const int m = mw + i * 16 + ml;
                *(float2*)&C[(size_t)m * DIMV + n] =
                    make_float2(acc[i][j][0] + b0, acc[i][j][1] + b1);
                *(float2*)&C[(size_t)(m + 8) * DIMV + n] =
                    make_float2(acc[i][j][2] + b0, acc[i][j][3] + b1);
            }
        }
    } else {
#pragma unroll
        for (int j = 0; j < 8; j++) {
            const int n = nw + j * 8 + nl;
            const float b0 = bias[n], b1 = bias[n + 1];
#pragma unroll
            for (int i = 0; i < 4; i++) {
                const int m = mw + i * 16 + ml;
                uint32_t h, l;
                psplit(acc[i][j][0] + b0, acc[i][j][1] + b1, h, l);
                *(uint32_t*)&Chi[(size_t)m * DIMV + n] = h;
                *(uint32_t*)&Clo[(size_t)m * DIMV + n] = l;
                psplit(acc[i][j][2] + b0, acc[i][j][3] + b1, h, l);
                *(uint32_t*)&Chi[(size_t)(m + 8) * DIMV + n] = h;
                *(uint32_t*)&Clo[(size_t)(m + 8) * DIMV + n] = l;
            }
        }
    }
}

// ---------------------------------------------------------------------------
// Fused RMSNorm + RoPE + history-key scaling; writes bf16 hi/lo planes
// directly (split fused into epilogue).
// ---------------------------------------------------------------------------
__global__ __launch_bounds__(256)
void normrope_kernel(const float* __restrict__ q, const float* __restrict__ k,
                     const float* __restrict__ rot,
                     const float* __restrict__ wq, const float* __restrict__ wk,
                     const float* __restrict__ hks, const int* __restrict__ oclp,
                     __nv_bfloat16* __restrict__ qhi, __nv_bfloat16* __restrict__ qlo,
                     __nv_bfloat16* __restrict__ khi, __nv_bfloat16* __restrict__ klo)
{
    const int r   = blockIdx.x;
    const int s   = r & (SEQ - 1);
    const int tid = threadIdx.x;
    const float* qrow = q + (size_t)r * DIMV;
    const float* krow = k + (size_t)r * DIMV;
    const int base = tid * 8;

    float qa[8], ka[8];
    {
        float4 t0 = *(const float4*)(qrow + base);
        float4 t1 = *(const float4*)(qrow + base + 4);
        qa[0]=t0.x; qa[1]=t0.y; qa[2]=t0.z; qa[3]=t0.w;
        qa[4]=t1.x; qa[5]=t1.y; qa[6]=t1.z; qa[7]=t1.w;
        float4 u0 = *(const float4*)(krow + base);
        float4 u1 = *(const float4*)(krow + base + 4);
        ka[0]=u0.x; ka[1]=u0.y; ka[2]=u0.z; ka[3]=u0.w;
        ka[4]=u1.x; ka[5]=u1.y; ka[6]=u1.z; ka[7]=u1.w;
    }

    float sq = 0.f, sk = 0.f;
#pragma unroll
    for (int i = 0; i < 8; i++) { sq = fmaf(qa[i], qa[i], sq); sk = fmaf(ka[i], ka[i], sk); }

    __shared__ float2 red[256];
    red[tid] = make_float2(sq, sk);
    __syncthreads();
#pragma unroll
    for (int off = 128; off > 0; off >>= 1) {
        if (tid < off) {
            red[tid].x += red[tid + off].x;
            red[tid].y += red[tid + off].y;
        }
        __syncthreads();
    }
    const float rq = rsqrtf(red[0].x * (1.f / DIMV) + EPSV);
    const float rk = rsqrtf(red[0].y * (1.f / DIMV) + EPSV);

    const int  hist    = SEQ - oclp[0];
    const bool is_hist = (s < hist);
    const float* rrow  = rot + (size_t)s * (2 * DHEAD);

    uint32_t qh[4], ql[4], kh[4], kl[4];
#pragma unroll
    for (int t = 0; t < 4; t++) {
        const int p = (base >> 1) + t;
        const int h = p >> 6;
        const int i = p & 63;
        const float c  = rrow[2*i];
        const float si = rrow[DHEAD + 2*i + 1];
        const int n = base + 2*t;
        float q1 = qa[2*t]     * rq * wq[n];
        float q2 = qa[2*t + 1] * rq * wq[n + 1];
        psplit(q1*c - q2*si, q1*si + q2*c, qh[t], ql[t]);
        float k1 = ka[2*t]     * rk * wk[n];
        float k2 = ka[2*t + 1] * rk * wk[n + 1];
        float ke  = k1*c - k2*si;
        float kod = k1*si + k2*c;
        if (is_hist) {
            const float sc = 1.f + 9.f / (1.f + __expf(-hks[h]));
            ke *= sc; kod *= sc;
        }
        psplit(ke, kod, kh[t], kl[t]);
    }
    *(uint4*)(qhi + (size_t)r * DIMV + base) = make_uint4(qh[0], qh[1], qh[2], qh[3]);
    *(uint4*)(qlo + (size_t)r * DIMV + base) = make_uint4(ql[0], ql[1], ql[2], ql[3]);
    *(uint4*)(khi + (size_t)r * DIMV + base) = make_uint4(kh[0], kh[1], kh[2], kh[3]);
    *(uint4*)(klo + (size_t)r * DIMV + base) = make_uint4(kl[0], kl[1], kl[2], kl[3]);
}

// ---------------------------------------------------------------------------
// Tensor-core flash attention, bf16 3-term. BQ=192 (12 warps x 16 q-rows),
// BKV=64 double-buffered. Q resident 96KB + KV 128KB = 224KB smem.
// Epilogue writes attn-out as bf16 hi/lo planes (split fused).
// ---------------------------------------------------------------------------
#define BQF 192
#define FATT_SMEM (98304 + 131072)     // 224 KB
#define FCL2 (0.08838834764831845f * 1.4426950408889634f)

__global__ __launch_bounds__(384, 1)
void flashmma_kernel(const __nv_bfloat16* __restrict__ Qhi, const __nv_bfloat16* __restrict__ Qlo,
                     const __nv_bfloat16* __restrict__ Khi, const __nv_bfloat16* __restrict__ Klo,
                     const __nv_bfloat16* __restrict__ Vhi, const __nv_bfloat16* __restrict__ Vlo,
                     __nv_bfloat16* __restrict__ Ohi, __nv_bfloat16* __restrict__ Olo)
{
    extern __shared__ __align__(1024) char smem[];
    const uint32_t sb   = smem_u32(smem);
    const int tid = threadIdx.x, wid = tid >> 5, lane = tid & 31;
    const int bh = blockIdx.y, b = bh >> 4, h = bh & 15;
    const int q0 = blockIdx.x * BQF;
    const size_t rowbase = (size_t)b * SEQ;
    const int hoff = h * DHEAD;

    const uint32_t smQh = sb;
    const uint32_t smQl = sb + 49152;      // 192*256
    const uint32_t smKV = sb + 98304;

    // Q tiles (hi+lo): 6144 x 16B chunks, 384 threads x 16 (rows clamped)
#pragma unroll
    for (int j = 0; j < 16; j++) {
        const int c  = tid + j * 384;
        const int p  = c / 3072;
        const int cc = c - p * 3072;
        const int r  = cc >> 4, ch = c & 15;
        const int rr = min(q0 + r, SEQ - 1);
        const uint32_t dst = (p ? smQl : smQh) + SWZ(r, ch);
        const __nv_bfloat16* src = (p ? Qlo : Qhi)
            + (rowbase + rr) * DIMV + hoff + ch * 8;
        CP_ASYNC16(dst, src);
    }
    // KV loader: warps 0-7 only (4096 chunks, clean 16/thread)
    auto load_kv = [&](int kv0, int buf) {
        if (tid < 256) {
            const uint32_t bo = smKV + buf * 65536;
#pragma unroll
            for (int j = 0; j < 16; j++) {
                const int c = tid + j * 256;
                const int p = c >> 10, r = (c >> 4) & 63, ch = c & 15;
                const __nv_bfloat16* pl = (p == 0) ? Khi : (p == 1) ? Klo : (p == 2) ? Vhi : Vlo;
                const uint32_t dst = bo + p * 16384 + SWZ(r, ch);
                CP_ASYNC16(dst, pl + (rowbase + kv0 + r) * DIMV + hoff + ch * 8);
            }
        }
    };
    load_kv(0, 0);
    CP_COMMIT();

    float co[16][4];
#pragma unroll
    for (int j = 0; j < 16; j++)
#pragma unroll
        for (int t = 0; t < 4; t++) co[j][t] = 0.f;
    float m0p = -1e30f, m1p = -1e30f, l0 = 0.f, l1 = 0.f;

    const int a_rl  = wid * 16 + (lane & 15);
    const int a_chx = lane >> 4;
    const int b_rl  = ((lane >> 4) << 3) + (lane & 7);
    const int b_chx = (lane >> 3) & 1;
    const int v_rl  = lane & 15;
    const int v_chx = lane >> 4;

    for (int s = 0; s < 32; s++) {
        const int buf = s & 1;
        if (s + 1 < 32) { load_kv((s + 1) * 64, buf ^ 1); CP_COMMIT(); CP_WAIT1(); }
        else            { CP_WAIT0(); }
        __syncthreads();

        const uint32_t Kh = smKV + buf * 65536;
        const uint32_t Kl = Kh + 16384;
        const uint32_t Vh = Kh + 32768;
        const uint32_t Vl = Kh + 49152;

        // ---- S = Q @ K^T (warp: 16x64) ----
        float cs[8][4];
#pragma unroll
        for (int j = 0; j < 8; j++)
#pragma unroll
            for (int t = 0; t < 4; t++) cs[j][t] = 0.f;

#pragma unroll
        for (int kk = 0; kk < 8; kk++) {
            uint32_t qh[4], ql[4], kh[8][2], kl[8][2];
            const uint32_t qa = SWZ(a_rl, 2 * kk + a_chx);
            ldsm4(qh, smQh + qa);
            ldsm4(ql, smQl + qa);
#pragma unroll
            for (int jj = 0; jj < 4; jj++) {
                const uint32_t ka = SWZ(16 * jj + b_rl, 2 * kk + b_chx);
                uint32_t t[4];
                ldsm4(t, Kh + ka);
                kh[2*jj][0] = t[0];   kh[2*jj][1] = t[1];
                kh[2*jj+1][0] = t[2]; kh[2*jj+1][1] = t[3];
                ldsm4(t, Kl + ka);
                kl[2*jj][0] = t[0];   kl[2*jj][1] = t[1];
                kl[2*jj+1][0] = t[2]; kl[2*jj+1][1] = t[3];
            }
#pragma unroll
            for (int j = 0; j < 8; j++) {
                mma16816(cs[j], qh, kh[j]);
                mma16816(cs[j], qh, kl[j]);
                mma16816(cs[j], ql, kh[j]);
            }
        }

        // ---- online softmax ----
        float mx0 = -1e30f, mx1 = -1e30f;
#pragma unroll
        for (int j = 0; j < 8; j++) {
            mx0 = fmaxf(mx0, fmaxf(cs[j][0], cs[j][1]));
            mx1 = fmaxf(mx1, fmaxf(cs[j][2], cs[j][3]));
        }
        mx0 = fmaxf(mx0, __shfl_xor_sync(0xffffffffu, mx0, 1));
        mx0 = fmaxf(mx0, __shfl_xor_sync(0xffffffffu, mx0, 2));
        mx1 = fmaxf(mx1, __shfl_xor_sync(0xffffffffu, mx1, 1));
        mx1 = fmaxf(mx1, __shfl_xor_sync(0xffffffffu, mx1, 2));
        const float mn0 = fmaxf(m0p, mx0);
        const float mn1 = fmaxf(m1p, mx1);
        float s0 = 0.f, s1 = 0.f;
#pragma unroll
        for (int j = 0; j < 8; j++) {
            cs[j][0] = exp2f((cs[j][0] - mn0) * FCL2); s0 += cs[j][0];
            cs[j][1] = exp2f((cs[j][1] - mn0) * FCL2); s0 += cs[j][1];
            cs[j][2] = exp2f((cs[j][2] - mn1) * FCL2); s1 += cs[j][2];
            cs[j][3] = exp2f((cs[j][3] - mn1) * FCL2); s1 += cs[j][3];
        }
        s0 += __shfl_xor_sync(0xffffffffu, s0, 1);
        s0 += __shfl_xor_sync(0xffffffffu, s0, 2);
        s1 += __shfl_xor_sync(0xffffffffu, s1, 1);
        s1 += __shfl_xor_sync(0xffffffffu, s1, 2);
        const float al0 = exp2f((m0p - mn0) * FCL2);
        const float al1 = exp2f((m1p - mn1) * FCL2);
        l0 = l0 * al0 + s0;  l1 = l1 * al1 + s1;
        m0p = mn0;  m1p = mn1;
#pragma unroll
        for (int j = 0; j < 16; j++) {
            co[j][0] *= al0; co[j][1] *= al0;
            co[j][2] *= al1; co[j][3] *= al1;
        }

        // ---- O += P @ V ----
#pragma unroll
        for (int t = 0; t < 4; t++) {
            uint32_t ph[4], pl4[4];
            psplit(cs[2*t][0],   cs[2*t][1],   ph[0], pl4[0]);
            psplit(cs[2*t][2],   cs[2*t][3],   ph[1], pl4[1]);
            psplit(cs[2*t+1][0], cs[2*t+1][1], ph[2], pl4[2]);
            psplit(cs[2*t+1][2], cs[2*t+1][3], ph[3], pl4[3]);
#pragma unroll
            for (int jp = 0; jp < 8; jp++) {
                const uint32_t va = SWZ(16 * t + v_rl, 2 * jp + v_chx);
                uint32_t th[4], tl[4];
                ldsm4t(th, Vh + va);
                ldsm4t(tl, Vl + va);
                mma16816(co[2*jp],   ph,  th);
                mma16816(co[2*jp+1], ph,  th + 2);
                mma16816(co[2*jp],   ph,  tl);
                mma16816(co[2*jp+1], ph,  tl + 2);
                mma16816(co[2*jp],   pl4, th);
                mma16816(co[2*jp+1], pl4, th + 2);
            }
        }
        __syncthreads();
    }

    // ---- epilogue: O/l, split to bf16 hi/lo, guarded for partial tile ----
    if (q0 + wid * 16 < SEQ) {
        const float i0 = 1.f / l0, i1 = 1.f / l1;
        const size_t r0 = rowbase + q0 + wid * 16 + (lane >> 2);
        const size_t r1 = r0 + 8;
        const int    cb = hoff + 2 * (lane & 3);
#pragma unroll
        for (int j = 0; j < 16; j++) {
            uint32_t hh, ll;
            psplit(co[j][0] * i0, co[j][1] * i0, hh, ll);
            *(uint32_t*)(Ohi + r0 * DIMV + cb + 8 * j) = hh;
            *(uint32_t*)(Olo + r0 * DIMV + cb + 8 * j) = ll;
            psplit(co[j][2] * i1, co[j][3] * i1, hh, ll);
            *(uint32_t*)(Ohi + r1 * DIMV + cb + 8 * j) = hh;
            *(uint32_t*)(Olo + r1 * DIMV + cb + 8 * j) = ll;
        }
    }
}

// ---------------------------------------------------------------------------
extern "C" void kernel_launch(void* const* d_in, const int* in_sizes, int n_in,
                              void* d_out, int out_size)
{
    const float* hs  = (const float*)d_in[0];
    const float* rot = (const float*)d_in[1];
    const float* Wq  = (const float*)d_in[2];
    const float* bq  = (const float*)d_in[3];
    const float* Wk  = (const float*)d_in[4];
    const float* bk  = (const float*)d_in[5];
    const float* Wv  = (const float*)d_in[6];
    const float* bv  = (const float*)d_in[7];
    const float* nqw = (const float*)d_in[8];
    const float* nkw = (const float*)d_in[9];
    const float* hks = (const float*)d_in[10];
    const float* Wo  = (const float*)d_in[11];
    const float* bo  = (const float*)d_in[12];
    const int*   ocl = (const int*)d_in[13];
    float* out = (float*)d_out;

    float *qp, *kp, *ap;
    cudaGetSymbolAddress((void**)&qp, g_q);
    cudaGetSymbolAddress((void**)&kp, g_k);
    cudaGetSymbolAddress((void**)&ap, g_attn);

    __nv_bfloat16 *ahi, *alo, *khi, *klo, *vhi, *vlo;
    __nv_bfloat16 *wqh, *wql, *wkh, *wkl, *wvh, *wvl, *woh, *wol;
    cudaGetSymbolAddress((void**)&ahi, g_ahi);
    cudaGetSymbolAddress((void**)&alo, g_alo);
    cudaGetSymbolAddress((void**)&khi, g_khi);
    cudaGetSymbolAddress((void**)&klo, g_klo);
    cudaGetSymbolAddress((void**)&vhi, g_vhi);
    cudaGetSymbolAddress((void**)&vlo, g_vlo);
    cudaGetSymbolAddress((void**)&wqh, g_wqhi);
    cudaGetSymbolAddress((void**)&wql, g_wqlo);
    cudaGetSymbolAddress((void**)&wkh, g_wkhi);
    cudaGetSymbolAddress((void**)&wkl, g_wklo);
    cudaGetSymbolAddress((void**)&wvh, g_wvhi);
    cudaGetSymbolAddress((void**)&wvl, g_wvlo);
    cudaGetSymbolAddress((void**)&woh, g_wohi);
    cudaGetSymbolAddress((void**)&wol, g_wolo);

    // attn-out bf16 planes alias the fp32 g_attn buffer (2 planes fit exactly)
    __nv_bfloat16* ohi = (__nv_bfloat16*)ap;
    __nv_bfloat16* olo = ohi + (size_t)MROWS * DIMV;

    const int nAct = MROWS * DIMV;       // 8.4M
    const int nW   = DIMV * DIMV;        // 4.2M

    split_kernel<<<nAct / 1024, 256>>>(hs, ahi, alo, nAct);
    split_kernel<<<nW / 1024, 256>>>(Wq, wqh, wql, nW);
    split_kernel<<<nW / 1024, 256>>>(Wk, wkh, wkl, nW);
    split_kernel<<<nW / 1024, 256>>>(Wv, wvh, wvl, nW);
    split_kernel<<<nW / 1024, 256>>>(Wo, woh, wol, nW);

    cudaFuncSetAttribute(gemm_mma_kernel,
                         cudaFuncAttributeMaxDynamicSharedMemorySize, GEMM_SMEM);
    dim3 gg(DIMV / 256, MROWS / 128);   // (8, 32)
    gemm_mma_kernel<<<gg, 256, GEMM_SMEM>>>(ahi, alo, wqh, wql, bq, qp, nullptr, nullptr);
    gemm_mma_kernel<<<gg, 256, GEMM_SMEM>>>(ahi, alo, wkh, wkl, bk, kp, nullptr, nullptr);
    gemm_mma_kernel<<<gg, 256, GEMM_SMEM>>>(ahi, alo, wvh, wvl, bv, nullptr, vhi, vlo);

    // normrope writes q/k bf16 planes directly (Q planes reuse ahi/alo)
    normrope_kernel<<<MROWS, 256>>>(qp, kp, rot, nqw, nkw, hks, ocl,
                                    ahi, alo, khi, klo);

    cudaFuncSetAttribute(flashmma_kernel,
                         cudaFuncAttributeMaxDynamicSharedMemorySize, FATT_SMEM);
    flashmma_kernel<<<dim3((SEQ + BQF - 1) / BQF, BATCH * HEADS), 384, FATT_SMEM>>>(
        ahi, alo, khi, klo, vhi, vlo, ohi, olo);

    gemm_mma_kernel<<<gg, 256, GEMM_SMEM>>>(ohi, olo, woh, wol, bo, out, nullptr, nullptr);
}

// round 13
// speedup vs baseline: 1.0521x; 1.0521x over previous
#include <cuda_runtime.h>
#include <cuda_bf16.h>
#include <math.h>
#include <cstdint>

#define DIMV    2048
#define SEQ     2048
#define BATCH   2
#define HEADS   16
#define DHEAD   128
#define MROWS   (BATCH*SEQ)   // 4096
#define EPSV    1e-5f

// ---------------- scratch (device globals; no allocation allowed) ----------
__device__ float g_q[(size_t)MROWS * DIMV];
__device__ float g_k[(size_t)MROWS * DIMV];
__device__ float g_attn[(size_t)MROWS * DIMV];   // reused as 2 bf16 planes of attn-out
__device__ __nv_bfloat16 g_ahi[(size_t)MROWS * DIMV];
__device__ __nv_bfloat16 g_alo[(size_t)MROWS * DIMV];
__device__ __nv_bfloat16 g_khi[(size_t)MROWS * DIMV];
__device__ __nv_bfloat16 g_klo[(size_t)MROWS * DIMV];
__device__ __nv_bfloat16 g_vhi[(size_t)MROWS * DIMV];
__device__ __nv_bfloat16 g_vlo[(size_t)MROWS * DIMV];
__device__ __nv_bfloat16 g_wqhi[(size_t)DIMV * DIMV];
__device__ __nv_bfloat16 g_wqlo[(size_t)DIMV * DIMV];
__device__ __nv_bfloat16 g_wkhi[(size_t)DIMV * DIMV];
__device__ __nv_bfloat16 g_wklo[(size_t)DIMV * DIMV];
__device__ __nv_bfloat16 g_wvhi[(size_t)DIMV * DIMV];
__device__ __nv_bfloat16 g_wvlo[(size_t)DIMV * DIMV];
__device__ __nv_bfloat16 g_wohi[(size_t)DIMV * DIMV];
__device__ __nv_bfloat16 g_wolo[(size_t)DIMV * DIMV];

// ---------------- arch-neutral tensor helpers (compute_103-safe) -----------
__device__ __forceinline__ uint32_t smem_u32(const void* p) {
    uint32_t a;
    asm("{ .reg .u64 t; cvta.to.shared.u64 t, %1; cvt.u32.u64 %0, t; }"
        : "=r"(a) : "l"(p));
    return a;
}
__device__ __forceinline__ void ldsm4(uint32_t* r, uint32_t addr) {
    asm volatile("ldmatrix.sync.aligned.m8n8.x4.shared.b16 {%0,%1,%2,%3}, [%4];"
                 : "=r"(r[0]), "=r"(r[1]), "=r"(r[2]), "=r"(r[3]) : "r"(addr));
}
__device__ __forceinline__ void ldsm4t(uint32_t* r, uint32_t addr) {
    asm volatile("ldmatrix.sync.aligned.m8n8.x4.trans.shared.b16 {%0,%1,%2,%3}, [%4];"
                 : "=r"(r[0]), "=r"(r[1]), "=r"(r[2]), "=r"(r[3]) : "r"(addr));
}
__device__ __forceinline__ void mma16816(float* c, const uint32_t* a, const uint32_t* b) {
    asm volatile("mma.sync.aligned.m16n8k16.row.col.f32.bf16.bf16.f32 "
                 "{%0,%1,%2,%3}, {%4,%5,%6,%7}, {%8,%9}, {%0,%1,%2,%3};"
                 : "+f"(c[0]), "+f"(c[1]), "+f"(c[2]), "+f"(c[3])
                 : "r"(a[0]), "r"(a[1]), "r"(a[2]), "r"(a[3]), "r"(b[0]), "r"(b[1]));
}
// pack two fp32 into bf16x2 hi + residual-lo bf16x2
__device__ __forceinline__ void psplit(float f0, float f1, uint32_t& h, uint32_t& l) {
    asm("cvt.rn.bf16x2.f32 %0, %1, %2;" : "=r"(h) : "f"(f1), "f"(f0));
    const float h0 = __uint_as_float(h << 16);
    const float h1 = __uint_as_float(h & 0xffff0000u);
    const float l0 = f0 - h0, l1 = f1 - h1;
    asm("cvt.rn.bf16x2.f32 %0, %1, %2;" : "=r"(l) : "f"(l1), "f"(l0));
}
#define CP_ASYNC16(dst, src) asm volatile("cp.async.cg.shared.global [%0], [%1], 16;" :: "r"(dst), "l"(src))
#define CP_COMMIT()          asm volatile("cp.async.commit_group;" ::: "memory")
#define CP_WAIT1()           asm volatile("cp.async.wait_group 1;" ::: "memory")
#define CP_WAIT0()           asm volatile("cp.async.wait_group 0;" ::: "memory")
// swizzled offset within a 256B-row tile (16B chunks)
__device__ __forceinline__ uint32_t SWZ(int r, int ch) {
    return (uint32_t)((r << 8) + (((ch & 7) ^ (r & 7)) << 4) + ((ch & 8) << 4));
}

// ---------------------------------------------------------------------------
// fp32 -> bf16 hi/lo split (vectorized x4)
// ---------------------------------------------------------------------------
__global__ __launch_bounds__(256)
void split_kernel(const float* __restrict__ x, __nv_bfloat16* __restrict__ hi,
                  __nv_bfloat16* __restrict__ lo, int n)
{
    int i = (blockIdx.x * blockDim.x + threadIdx.x) * 4;
    if (i >= n) return;
    float4 v = *(const float4*)(x + i);
    uint32_t h0, l0, h1, l1;
    psplit(v.x, v.y, h0, l0);
    psplit(v.z, v.w, h1, l1);
    *(uint2*)(hi + i) = make_uint2(h0, h1);
    *(uint2*)(lo + i) = make_uint2(l0, l1);
}

// ---------------------------------------------------------------------------
// bf16 3-term mma.sync GEMM (R6-verified core). Epilogue writes either fp32 C
// (+bias) or split bf16 hi/lo planes (+bias) when Chi != nullptr.
// ---------------------------------------------------------------------------
#define BUF_STRIDE 98304
#define GEMM_SMEM  (2 * BUF_STRIDE)

__global__ __launch_bounds__(256, 1)
void gemm_mma_kernel(const __nv_bfloat16* __restrict__ Ahi, const __nv_bfloat16* __restrict__ Alo,
                     const __nv_bfloat16* __restrict__ Bhi, const __nv_bfloat16* __restrict__ Blo,
                     const float* __restrict__ bias, float* __restrict__ C,
                     __nv_bfloat16* __restrict__ Chi, __nv_bfloat16* __restrict__ Clo)
{
    extern __shared__ __align__(1024) char smem[];
    const uint32_t sb = smem_u32(smem);

    const int tid  = threadIdx.x;
    const int wid  = tid >> 5;
    const int lane = tid & 31;
    const int wm   = wid >> 2;
    const int wn   = wid & 3;
    const int m0   = blockIdx.y * 128;
    const int n0   = blockIdx.x * 256;

    auto load_stage = [&](int k0, int buf) {
        const uint32_t bo = sb + buf * BUF_STRIDE;
#pragma unroll
        for (int j = 0; j < 8; j++) {
            const int c  = tid + j * 256;
            const int p  = c >> 10;
            const int r  = (c >> 3) & 127;
            const int ch = c & 7;
            const uint32_t dst = bo + p * 16384 + (r << 7) + ((ch ^ (r & 7)) << 4);
            const __nv_bfloat16* src = (p ? Alo : Ahi)
                + (size_t)(m0 + r) * DIMV + k0 + ch * 8;
            CP_ASYNC16(dst, src);
        }
#pragma unroll
        for (int j = 0; j < 16; j++) {
            const int c  = tid + j * 256;
            const int p  = c >> 11;
            const int r  = (c >> 3) & 255;
            const int ch = c & 7;
            const uint32_t dst = bo + 32768 + p * 32768 + (r << 7) + ((ch ^ (r & 7)) << 4);
            const __nv_bfloat16* src = (p ? Blo : Bhi)
                + (size_t)(n0 + r) * DIMV + k0 + ch * 8;
            CP_ASYNC16(dst, src);
        }
    };

    float acc[4][8][4];
#pragma unroll
    for (int i = 0; i < 4; i++)
#pragma unroll
        for (int j = 0; j < 8; j++)
#pragma unroll
            for (int t = 0; t < 4; t++) acc[i][j][t] = 0.f;

    const int a_row = wm * 64 + (lane & 15);
    const int a_chx = lane >> 4;
    const int b_row = wn * 64 + ((lane >> 4) << 3) + (lane & 7);
    const int b_chx = (lane >> 3) & 1;

    load_stage(0, 0);
    CP_COMMIT();

    for (int s = 0; s < 32; s++) {
        const int buf = s & 1;
        if (s + 1 < 32) { load_stage((s + 1) * 64, buf ^ 1); CP_COMMIT(); CP_WAIT1(); }
        else            { CP_WAIT0(); }
        __syncthreads();

        const uint32_t aH = sb + buf * BUF_STRIDE;
        const uint32_t aL = aH + 16384;
        const uint32_t bH = aH + 32768;
        const uint32_t bL = bH + 32768;

#pragma unroll
        for (int kk8 = 0; kk8 < 4; kk8++) {
            uint32_t ah[4][4], al[4][4], bh[8][2], bl[8][2];
            const int ach = kk8 * 2 + a_chx;
#pragma unroll
            for (int i = 0; i < 4; i++) {
                const int r = a_row + i * 16;
                const uint32_t ad = (r << 7) + ((ach ^ (r & 7)) << 4);
                ldsm4(ah[i], aH + ad);
                ldsm4(al[i], aL + ad);
            }
            const int bch = kk8 * 2 + b_chx;
#pragma unroll
            for (int jj = 0; jj < 4; jj++) {
                const int r = b_row + jj * 16;
                const uint32_t bd = (r << 7) + ((bch ^ (r & 7)) << 4);
                uint32_t t[4];
                ldsm4(t, bH + bd);
                bh[2*jj][0] = t[0];   bh[2*jj][1] = t[1];
                bh[2*jj+1][0] = t[2]; bh[2*jj+1][1] = t[3];
                ldsm4(t, bL + bd);
                bl[2*jj][0] = t[0];   bl[2*jj][1] = t[1];
                bl[2*jj+1][0] = t[2]; bl[2*jj+1][1] = t[3];
            }
#pragma unroll
            for (int i = 0; i < 4; i++)
#pragma unroll
                for (int j = 0; j < 8; j++) {
                    mma16816(acc[i][j], ah[i], bh[j]);
                    mma16816(acc[i][j], ah[i], bl[j]);
                    mma16816(acc[i][j], al[i], bh[j]);
                }
        }
        __syncthreads();
    }

    const int mw = m0 + wm * 64;
    const int nw = n0 + wn * 64;
    const int ml = lane >> 2;
    const int nl = (lane & 3) * 2;
    if (Chi == nullptr) {
#pragma unroll
        for (int j = 0; j < 8; j++) {
            const int n = nw + j * 8 + nl;
            const float b0 = bias[n], b1 = bias[n + 1];
#pragma unroll
            for (int i = 0; i < 4; i++) {
                const int m = mw + i * 16 + ml;
                *(float2*)&C[(size_t)m * DIMV + n] =
                    make_float2(acc[i][j][0] + b0, acc[i][j][1] + b1);
                *(float2*)&C[(size_t)(m + 8) * DIMV + n] =
                    make_float2(acc[i][j][2] + b0, acc[i][j][3] + b1);
            }
        }
    } else {
#pragma unroll
        for (int j = 0; j < 8; j++) {
            const int n = nw + j * 8 + nl;
            const float b0 = bias[n], b1 = bias[n + 1];
#pragma unroll
            for (int i = 0; i < 4; i++) {
                const int m = mw + i * 16 + ml;
                uint32_t h, l;
                psplit(acc[i][j][0] + b0, acc[i][j][1] + b1, h, l);
                *(uint32_t*)&Chi[(size_t)m * DIMV + n] = h;
                *(uint32_t*)&Clo[(size_t)m * DIMV + n] = l;
                psplit(acc[i][j][2] + b0, acc[i][j][3] + b1, h, l);
                *(uint32_t*)&Chi[(size_t)(m + 8) * DIMV + n] = h;
                *(uint32_t*)&Clo[(size_t)(m + 8) * DIMV + n] = l;
            }
        }
    }
}

// ---------------------------------------------------------------------------
// Fused RMSNorm + RoPE + history-key scaling; writes bf16 hi/lo planes
// directly (split fused into epilogue).
// ---------------------------------------------------------------------------
__global__ __launch_bounds__(256)
void normrope_kernel(const float* __restrict__ q, const float* __restrict__ k,
                     const float* __restrict__ rot,
                     const float* __restrict__ wq, const float* __restrict__ wk,
                     const float* __restrict__ hks, const int* __restrict__ oclp,
                     __nv_bfloat16* __restrict__ qhi, __nv_bfloat16* __restrict__ qlo,
                     __nv_bfloat16* __restrict__ khi, __nv_bfloat16* __restrict__ klo)
{
    const int r   = blockIdx.x;
    const int s   = r & (SEQ - 1);
    const int tid = threadIdx.x;
    const float* qrow = q + (size_t)r * DIMV;
    const float* krow = k + (size_t)r * DIMV;
    const int base = tid * 8;

    float qa[8], ka[8];
    {
        float4 t0 = *(const float4*)(qrow + base);
        float4 t1 = *(const float4*)(qrow + base + 4);
        qa[0]=t0.x; qa[1]=t0.y; qa[2]=t0.z; qa[3]=t0.w;
        qa[4]=t1.x; qa[5]=t1.y; qa[6]=t1.z; qa[7]=t1.w;
        float4 u0 = *(const float4*)(krow + base);
        float4 u1 = *(const float4*)(krow + base + 4);
        ka[0]=u0.x; ka[1]=u0.y; ka[2]=u0.z; ka[3]=u0.w;
        ka[4]=u1.x; ka[5]=u1.y; ka[6]=u1.z; ka[7]=u1.w;
    }

    float sq = 0.f, sk = 0.f;
#pragma unroll
    for (int i = 0; i < 8; i++) { sq = fmaf(qa[i], qa[i], sq); sk = fmaf(ka[i], ka[i], sk); }

    __shared__ float2 red[256];
    red[tid] = make_float2(sq, sk);
    __syncthreads();
#pragma unroll
    for (int off = 128; off > 0; off >>= 1) {
        if (tid < off) {
            red[tid].x += red[tid + off].x;
            red[tid].y += red[tid + off].y;
        }
        __syncthreads();
    }
    const float rq = rsqrtf(red[0].x * (1.f / DIMV) + EPSV);
    const float rk = rsqrtf(red[0].y * (1.f / DIMV) + EPSV);

    const int  hist    = SEQ - oclp[0];
    const bool is_hist = (s < hist);
    const float* rrow  = rot + (size_t)s * (2 * DHEAD);

    uint32_t qh[4], ql[4], kh[4], kl[4];
#pragma unroll
    for (int t = 0; t < 4; t++) {
        const int p = (base >> 1) + t;
        const int h = p >> 6;
        const int i = p & 63;
        const float c  = rrow[2*i];
        const float si = rrow[DHEAD + 2*i + 1];
        const int n = base + 2*t;
        float q1 = qa[2*t]     * rq * wq[n];
        float q2 = qa[2*t + 1] * rq * wq[n + 1];
        psplit(q1*c - q2*si, q1*si + q2*c, qh[t], ql[t]);
        float k1 = ka[2*t]     * rk * wk[n];
        float k2 = ka[2*t + 1] * rk * wk[n + 1];
        float ke  = k1*c - k2*si;
        float kod = k1*si + k2*c;
        if (is_hist) {
            const float sc = 1.f + 9.f / (1.f + __expf(-hks[h]));
            ke *= sc; kod *= sc;
        }
        psplit(ke, kod, kh[t], kl[t]);
    }
    *(uint4*)(qhi + (size_t)r * DIMV + base) = make_uint4(qh[0], qh[1], qh[2], qh[3]);
    *(uint4*)(qlo + (size_t)r * DIMV + base) = make_uint4(ql[0], ql[1], ql[2], ql[3]);
    *(uint4*)(khi + (size_t)r * DIMV + base) = make_uint4(kh[0], kh[1], kh[2], kh[3]);
    *(uint4*)(klo + (size_t)r * DIMV + base) = make_uint4(kl[0], kl[1], kl[2], kl[3]);
}

// ---------------------------------------------------------------------------
// Tensor-core flash attention, bf16 3-term (R9-verified shape: BQ=128,
// 256 threads, 8 warps x 16 q-rows, BKV=64 double-buffered, 192KB smem).
// Epilogue writes attn-out as bf16 hi/lo planes (split fused).
// ---------------------------------------------------------------------------
#define FATT_SMEM 196608
#define FCL2 (0.08838834764831845f * 1.4426950408889634f)

__global__ __launch_bounds__(256, 1)
void flashmma_kernel(const __nv_bfloat16* __restrict__ Qhi, const __nv_bfloat16* __restrict__ Qlo,
                     const __nv_bfloat16* __restrict__ Khi, const __nv_bfloat16* __restrict__ Klo,
                     const __nv_bfloat16* __restrict__ Vhi, const __nv_bfloat16* __restrict__ Vlo,
                     __nv_bfloat16* __restrict__ Ohi, __nv_bfloat16* __restrict__ Olo)
{
    extern __shared__ __align__(1024) char smem[];
    const uint32_t sb   = smem_u32(smem);
    const int tid = threadIdx.x, wid = tid >> 5, lane = tid & 31;
    const int bh = blockIdx.y, b = bh >> 4, h = bh & 15;
    const int q0 = blockIdx.x * 128;
    const size_t rowbase = (size_t)b * SEQ;
    const int hoff = h * DHEAD;

    const uint32_t smQh = sb;
    const uint32_t smQl = sb + 32768;
    const uint32_t smKV = sb + 65536;

    // Q tiles (hi+lo): 4096 x 16B chunks
#pragma unroll
    for (int j = 0; j < 16; j++) {
        const int c = tid + j * 256;
        const int p = c >> 11, r = (c >> 4) & 127, ch = c & 15;
        const uint32_t dst = (p ? smQl : smQh) + SWZ(r, ch);
        const __nv_bfloat16* src = (p ? Qlo : Qhi)
            + (rowbase + q0 + r) * DIMV + hoff + ch * 8;
        CP_ASYNC16(dst, src);
    }
    auto load_kv = [&](int kv0, int buf) {
        const uint32_t bo = smKV + buf * 65536;
#pragma unroll
        for (int j = 0; j < 16; j++) {
            const int c = tid + j * 256;
            const int p = c >> 10, r = (c >> 4) & 63, ch = c & 15;
            const __nv_bfloat16* pl = (p == 0) ? Khi : (p == 1) ? Klo : (p == 2) ? Vhi : Vlo;
            const uint32_t dst = bo + p * 16384 + SWZ(r, ch);
            CP_ASYNC16(dst, pl + (rowbase + kv0 + r) * DIMV + hoff + ch * 8);
        }
    };
    load_kv(0, 0);
    CP_COMMIT();

    float co[16][4];
#pragma unroll
    for (int j = 0; j < 16; j++)
#pragma unroll
        for (int t = 0; t < 4; t++) co[j][t] = 0.f;
    float m0p = -1e30f, m1p = -1e30f, l0 = 0.f, l1 = 0.f;

    const int a_rl  = wid * 16 + (lane & 15);
    const int a_chx = lane >> 4;
    const int b_rl  = ((lane >> 4) << 3) + (lane & 7);
    const int b_chx = (lane >> 3) & 1;
    const int v_rl  = lane & 15;
    const int v_chx = lane >> 4;

    for (int s = 0; s < 32; s++) {
        const int buf = s & 1;
        if (s + 1 < 32) { load_kv((s + 1) * 64, buf ^ 1); CP_COMMIT(); CP_WAIT1(); }
        else            { CP_WAIT0(); }
        __syncthreads();

        const uint32_t Kh = smKV + buf * 65536;
        const uint32_t Kl = Kh + 16384;
        const uint32_t Vh = Kh + 32768;
        const uint32_t Vl = Kh + 49152;

        // ---- S = Q @ K^T (warp: 16x64) ----
        float cs[8][4];
#pragma unroll
        for (int j = 0; j < 8; j++)
#pragma unroll
            for (int t = 0; t < 4; t++) cs[j][t] = 0.f;

#pragma unroll
        for (int kk = 0; kk < 8; kk++) {
            uint32_t qh[4], ql[4], kh[8][2], kl[8][2];
            const uint32_t qa = SWZ(a_rl, 2 * kk + a_chx);
            ldsm4(qh, smQh + qa);
            ldsm4(ql, smQl + qa);
#pragma unroll
            for (int jj = 0; jj < 4; jj++) {
                const uint32_t ka = SWZ(16 * jj + b_rl, 2 * kk + b_chx);
                uint32_t t[4];
                ldsm4(t, Kh + ka);
                kh[2*jj][0] = t[0];   kh[2*jj][1] = t[1];
                kh[2*jj+1][0] = t[2]; kh[2*jj+1][1] = t[3];
                ldsm4(t, Kl + ka);
                kl[2*jj][0] = t[0];   kl[2*jj][1] = t[1];
                kl[2*jj+1][0] = t[2]; kl[2*jj+1][1] = t[3];
            }
#pragma unroll
            for (int j = 0; j < 8; j++) {
                mma16816(cs[j], qh, kh[j]);
                mma16816(cs[j], qh, kl[j]);
                mma16816(cs[j], ql, kh[j]);
            }
        }

        // ---- online softmax ----
        float mx0 = -1e30f, mx1 = -1e30f;
#pragma unroll
        for (int j = 0; j < 8; j++) {
            mx0 = fmaxf(mx0, fmaxf(cs[j][0], cs[j][1]));
            mx1 = fmaxf(mx1, fmaxf(cs[j][2], cs[j][3]));
        }
        mx0 = fmaxf(mx0, __shfl_xor_sync(0xffffffffu, mx0, 1));
        mx0 = fmaxf(mx0, __shfl_xor_sync(0xffffffffu, mx0, 2));
        mx1 = fmaxf(mx1, __shfl_xor_sync(0xffffffffu, mx1, 1));
        mx1 = fmaxf(mx1, __shfl_xor_sync(0xffffffffu, mx1, 2));
        const float mn0 = fmaxf(m0p, mx0);
        const float mn1 = fmaxf(m1p, mx1);
        float s0 = 0.f, s1 = 0.f;
#pragma unroll
        for (int j = 0; j < 8; j++) {
            cs[j][0] = exp2f((cs[j][0] - mn0) * FCL2); s0 += cs[j][0];
            cs[j][1] = exp2f((cs[j][1] - mn0) * FCL2); s0 += cs[j][1];
            cs[j][2] = exp2f((cs[j][2] - mn1) * FCL2); s1 += cs[j][2];
            cs[j][3] = exp2f((cs[j][3] - mn1) * FCL2); s1 += cs[j][3];
        }
        s0 += __shfl_xor_sync(0xffffffffu, s0, 1);
        s0 += __shfl_xor_sync(0xffffffffu, s0, 2);
        s1 += __shfl_xor_sync(0xffffffffu, s1, 1);
        s1 += __shfl_xor_sync(0xffffffffu, s1, 2);
        const float al0 = exp2f((m0p - mn0) * FCL2);
        const float al1 = exp2f((m1p - mn1) * FCL2);
        l0 = l0 * al0 + s0;  l1 = l1 * al1 + s1;
        m0p = mn0;  m1p = mn1;
#pragma unroll
        for (int j = 0; j < 16; j++) {
            co[j][0] *= al0; co[j][1] *= al0;
            co[j][2] *= al1; co[j][3] *= al1;
        }

        // ---- O += P @ V (P frags from S accum, split hi/lo in-register) ----
#pragma unroll
        for (int t = 0; t < 4; t++) {
            uint32_t ph[4], pl4[4];
            psplit(cs[2*t][0],   cs[2*t][1],   ph[0], pl4[0]);
            psplit(cs[2*t][2],   cs[2*t][3],   ph[1], pl4[1]);
            psplit(cs[2*t+1][0], cs[2*t+1][1], ph[2], pl4[2]);
            psplit(cs[2*t+1][2], cs[2*t+1][3], ph[3], pl4[3]);
#pragma unroll
            for (int jp = 0; jp < 8; jp++) {
                const uint32_t va = SWZ(16 * t + v_rl, 2 * jp + v_chx);
                uint32_t th[4], tl[4];
                ldsm4t(th, Vh + va);
                ldsm4t(tl, Vl + va);
                mma16816(co[2*jp],   ph,  th);
                mma16816(co[2*jp+1], ph,  th + 2);
                mma16816(co[2*jp],   ph,  tl);
                mma16816(co[2*jp+1], ph,  tl + 2);
                mma16816(co[2*jp],   pl4, th);
                mma16816(co[2*jp+1], pl4, th + 2);
            }
        }
        __syncthreads();
    }

    // ---- epilogue: O/l, split to bf16 hi/lo planes ----
    const float i0 = 1.f / l0, i1 = 1.f / l1;
    const size_t r0 = rowbase + q0 + wid * 16 + (lane >> 2);
    const size_t r1 = r0 + 8;
    const int    cb = hoff + 2 * (lane & 3);
#pragma unroll
    for (int j = 0; j < 16; j++) {
        uint32_t hh, ll;
        psplit(co[j][0] * i0, co[j][1] * i0, hh, ll);
        *(uint32_t*)(Ohi + r0 * DIMV + cb + 8 * j) = hh;
        *(uint32_t*)(Olo + r0 * DIMV + cb + 8 * j) = ll;
        psplit(co[j][2] * i1, co[j][3] * i1, hh, ll);
        *(uint32_t*)(Ohi + r1 * DIMV + cb + 8 * j) = hh;
        *(uint32_t*)(Olo + r1 * DIMV + cb + 8 * j) = ll;
    }
}

// ---------------------------------------------------------------------------
extern "C" void kernel_launch(void* const* d_in, const int* in_sizes, int n_in,
                              void* d_out, int out_size)
{
    const float* hs  = (const float*)d_in[0];
    const float* rot = (const float*)d_in[1];
    const float* Wq  = (const float*)d_in[2];
    const float* bq  = (const float*)d_in[3];
    const float* Wk  = (const float*)d_in[4];
    const float* bk  = (const float*)d_in[5];
    const float* Wv  = (const float*)d_in[6];
    const float* bv  = (const float*)d_in[7];
    const float* nqw = (const float*)d_in[8];
    const float* nkw = (const float*)d_in[9];
    const float* hks = (const float*)d_in[10];
    const float* Wo  = (const float*)d_in[11];
    const float* bo  = (const float*)d_in[12];
    const int*   ocl = (const int*)d_in[13];
    float* out = (float*)d_out;

    float *qp, *kp, *ap;
    cudaGetSymbolAddress((void**)&qp, g_q);
    cudaGetSymbolAddress((void**)&kp, g_k);
    cudaGetSymbolAddress((void**)&ap, g_attn);

    __nv_bfloat16 *ahi, *alo, *khi, *klo, *vhi, *vlo;
    __nv_bfloat16 *wqh, *wql, *wkh, *wkl, *wvh, *wvl, *woh, *wol;
    cudaGetSymbolAddress((void**)&ahi, g_ahi);
    cudaGetSymbolAddress((void**)&alo, g_alo);
    cudaGetSymbolAddress((void**)&khi, g_khi);
    cudaGetSymbolAddress((void**)&klo, g_klo);
    cudaGetSymbolAddress((void**)&vhi, g_vhi);
    cudaGetSymbolAddress((void**)&vlo, g_vlo);
    cudaGetSymbolAddress((void**)&wqh, g_wqhi);
    cudaGetSymbolAddress((void**)&wql, g_wqlo);
    cudaGetSymbolAddress((void**)&wkh, g_wkhi);
    cudaGetSymbolAddress((void**)&wkl, g_wklo);
    cudaGetSymbolAddress((void**)&wvh, g_wvhi);
    cudaGetSymbolAddress((void**)&wvl, g_wvlo);
    cudaGetSymbolAddress((void**)&woh, g_wohi);
    cudaGetSymbolAddress((void**)&wol, g_wolo);

    // attn-out bf16 planes alias the fp32 g_attn buffer (2 planes fit exactly)
    __nv_bfloat16* ohi = (__nv_bfloat16*)ap;
    __nv_bfloat16* olo = ohi + (size_t)MROWS * DIMV;

    const int nAct = MROWS * DIMV;       // 8.4M
    const int nW   = DIMV * DIMV;        // 4.2M

    split_kernel<<<nAct / 1024, 256>>>(hs, ahi, alo, nAct);
    split_kernel<<<nW / 1024, 256>>>(Wq, wqh, wql, nW);
    split_kernel<<<nW / 1024, 256>>>(Wk, wkh, wkl, nW);
    split_kernel<<<nW / 1024, 256>>>(Wv, wvh, wvl, nW);
    split_kernel<<<nW / 1024, 256>>>(Wo, woh, wol, nW);

    cudaFuncSetAttribute(gemm_mma_kernel,
                         cudaFuncAttributeMaxDynamicSharedMemorySize, GEMM_SMEM);
    dim3 gg(DIMV / 256, MROWS / 128);   // (8, 32)
    gemm_mma_kernel<<<gg, 256, GEMM_SMEM>>>(ahi, alo, wqh, wql, bq, qp, nullptr, nullptr);
    gemm_mma_kernel<<<gg, 256, GEMM_SMEM>>>(ahi, alo, wkh, wkl, bk, kp, nullptr, nullptr);
    gemm_mma_kernel<<<gg, 256, GEMM_SMEM>>>(ahi, alo, wvh, wvl, bv, nullptr, vhi, vlo);

    // normrope writes q/k bf16 planes directly (Q planes reuse ahi/alo)
    normrope_kernel<<<MROWS, 256>>>(qp, kp, rot, nqw, nkw, hks, ocl,
                                    ahi, alo, khi, klo);

    cudaFuncSetAttribute(flashmma_kernel,
                         cudaFuncAttributeMaxDynamicSharedMemorySize, FATT_SMEM);
    flashmma_kernel<<<dim3(SEQ / 128, BATCH * HEADS), 256, FATT_SMEM>>>(
        ahi, alo, khi, klo, vhi, vlo, ohi, olo);

    gemm_mma_kernel<<<gg, 256, GEMM_SMEM>>>(ohi, olo, woh, wol, bo, out, nullptr, nullptr);
}

// round 15
// speedup vs baseline: 1.0521x; 1.0000x over previous
#include <cuda_runtime.h>
#include <cuda_bf16.h>
#include <math.h>
#include <cstdint>

#define DIMV    2048
#define SEQ     2048
#define BATCH   2
#define HEADS   16
#define DHEAD   128
#define MROWS   (BATCH*SEQ)   // 4096
#define EPSV    1e-5f

// ---------------- scratch (device globals; no allocation allowed) ----------
__device__ float g_q[(size_t)MROWS * DIMV];
__device__ float g_k[(size_t)MROWS * DIMV];
__device__ float g_attn[(size_t)MROWS * DIMV];   // reused as 2 bf16 planes of attn-out
__device__ __nv_bfloat16 g_ahi[(size_t)MROWS * DIMV];
__device__ __nv_bfloat16 g_alo[(size_t)MROWS * DIMV];
__device__ __nv_bfloat16 g_khi[(size_t)MROWS * DIMV];
__device__ __nv_bfloat16 g_klo[(size_t)MROWS * DIMV];
__device__ __nv_bfloat16 g_vhi[(size_t)MROWS * DIMV];
__device__ __nv_bfloat16 g_vlo[(size_t)MROWS * DIMV];
__device__ __nv_bfloat16 g_wqhi[(size_t)DIMV * DIMV];
__device__ __nv_bfloat16 g_wqlo[(size_t)DIMV * DIMV];
__device__ __nv_bfloat16 g_wkhi[(size_t)DIMV * DIMV];
__device__ __nv_bfloat16 g_wklo[(size_t)DIMV * DIMV];
__device__ __nv_bfloat16 g_wvhi[(size_t)DIMV * DIMV];
__device__ __nv_bfloat16 g_wvlo[(size_t)DIMV * DIMV];
__device__ __nv_bfloat16 g_wohi[(size_t)DIMV * DIMV];
__device__ __nv_bfloat16 g_wolo[(size_t)DIMV * DIMV];

// ---------------- arch-neutral tensor helpers (compute_103-safe) -----------
__device__ __forceinline__ uint32_t smem_u32(const void* p) {
    uint32_t a;
    asm("{ .reg .u64 t; cvta.to.shared.u64 t, %1; cvt.u32.u64 %0, t; }"
        : "=r"(a) : "l"(p));
    return a;
}
__device__ __forceinline__ void ldsm4(uint32_t* r, uint32_t addr) {
    asm volatile("ldmatrix.sync.aligned.m8n8.x4.shared.b16 {%0,%1,%2,%3}, [%4];"
                 : "=r"(r[0]), "=r"(r[1]), "=r"(r[2]), "=r"(r[3]) : "r"(addr));
}
__device__ __forceinline__ void ldsm4t(uint32_t* r, uint32_t addr) {
    asm volatile("ldmatrix.sync.aligned.m8n8.x4.trans.shared.b16 {%0,%1,%2,%3}, [%4];"
                 : "=r"(r[0]), "=r"(r[1]), "=r"(r[2]), "=r"(r[3]) : "r"(addr));
}
__device__ __forceinline__ void mma16816(float* c, const uint32_t* a, const uint32_t* b) {
    asm volatile("mma.sync.aligned.m16n8k16.row.col.f32.bf16.bf16.f32 "
                 "{%0,%1,%2,%3}, {%4,%5,%6,%7}, {%8,%9}, {%0,%1,%2,%3};"
                 : "+f"(c[0]), "+f"(c[1]), "+f"(c[2]), "+f"(c[3])
                 : "r"(a[0]), "r"(a[1]), "r"(a[2]), "r"(a[3]), "r"(b[0]), "r"(b[1]));
}
// pack two fp32 into bf16x2 hi + residual-lo bf16x2
__device__ __forceinline__ void psplit(float f0, float f1, uint32_t& h, uint32_t& l) {
    asm("cvt.rn.bf16x2.f32 %0, %1, %2;" : "=r"(h) : "f"(f1), "f"(f0));
    const float h0 = __uint_as_float(h << 16);
    const float h1 = __uint_as_float(h & 0xffff0000u);
    const float l0 = f0 - h0, l1 = f1 - h1;
    asm("cvt.rn.bf16x2.f32 %0, %1, %2;" : "=r"(l) : "f"(l1), "f"(l0));
}
#define CP_ASYNC16(dst, src) asm volatile("cp.async.cg.shared.global [%0], [%1], 16;" :: "r"(dst), "l"(src))
#define CP_COMMIT()          asm volatile("cp.async.commit_group;" ::: "memory")
#define CP_WAIT1()           asm volatile("cp.async.wait_group 1;" ::: "memory")
#define CP_WAIT0()           asm volatile("cp.async.wait_group 0;" ::: "memory")
// swizzled offset within a 256B-row tile (16B chunks)
__device__ __forceinline__ uint32_t SWZ(int r, int ch) {
    return (uint32_t)((r << 8) + (((ch & 7) ^ (r & 7)) << 4) + ((ch & 8) << 4));
}

// ---------------------------------------------------------------------------
// merged fp32 -> bf16 hi/lo split: 5 regions in one launch (grid.y selects)
// ---------------------------------------------------------------------------
__global__ __launch_bounds__(256)
void split5_kernel(const float* __restrict__ x0, __nv_bfloat16* h0, __nv_bfloat16* l0v, int n0,
                   const float* __restrict__ x1, __nv_bfloat16* h1, __nv_bfloat16* l1v, int n1,
                   const float* __restrict__ x2, __nv_bfloat16* h2, __nv_bfloat16* l2v, int n2,
                   const float* __restrict__ x3, __nv_bfloat16* h3, __nv_bfloat16* l3v, int n3,
                   const float* __restrict__ x4, __nv_bfloat16* h4, __nv_bfloat16* l4v, int n4)
{
    const int rg = blockIdx.y;
    const float* x;
    __nv_bfloat16 *hi, *lo;
    int n;
    switch (rg) {
        case 0: x = x0; hi = h0; lo = l0v; n = n0; break;
        case 1: x = x1; hi = h1; lo = l1v; n = n1; break;
        case 2: x = x2; hi = h2; lo = l2v; n = n2; break;
        case 3: x = x3; hi = h3; lo = l3v; n = n3; break;
        default: x = x4; hi = h4; lo = l4v; n = n4; break;
    }
    int i = (blockIdx.x * blockDim.x + threadIdx.x) * 4;
    if (i >= n) return;
    float4 v = *(const float4*)(x + i);
    uint32_t a, b, c, d;
    psplit(v.x, v.y, a, b);
    psplit(v.z, v.w, c, d);
    *(uint2*)(hi + i) = make_uint2(a, c);
    *(uint2*)(lo + i) = make_uint2(b, d);
}

// ---------------------------------------------------------------------------
// fp32 -> bf16 hi/lo split (single region; used for attn-out if needed)
// ---------------------------------------------------------------------------
__global__ __launch_bounds__(256)
void split_kernel(const float* __restrict__ x, __nv_bfloat16* __restrict__ hi,
                  __nv_bfloat16* __restrict__ lo, int n)
{
    int i = (blockIdx.x * blockDim.x + threadIdx.x) * 4;
    if (i >= n) return;
    float4 v = *(const float4*)(x + i);
    uint32_t h0, l0, h1, l1;
    psplit(v.x, v.y, h0, l0);
    psplit(v.z, v.w, h1, l1);
    *(uint2*)(hi + i) = make_uint2(h0, h1);
    *(uint2*)(lo + i) = make_uint2(l0, l1);
}

// ---------------------------------------------------------------------------
// bf16 3-term mma.sync GEMM (R6-verified core), merged-QKV aware:
// grid.z selects weight/bias/output. z output: fp32 C or bf16 hi/lo planes.
// ---------------------------------------------------------------------------
#define BUF_STRIDE 98304
#define GEMM_SMEM  (2 * BUF_STRIDE)

struct GemmJob {
    const __nv_bfloat16* Bhi;
    const __nv_bfloat16* Blo;
    const float* bias;
    float* C;                    // fp32 output (nullptr -> plane output)
    __nv_bfloat16* Chi;
    __nv_bfloat16* Clo;
};

__global__ __launch_bounds__(256, 1)
void gemm_mma_kernel(const __nv_bfloat16* __restrict__ Ahi, const __nv_bfloat16* __restrict__ Alo,
                     GemmJob j0, GemmJob j1, GemmJob j2)
{
    extern __shared__ __align__(1024) char smem[];
    const uint32_t sb = smem_u32(smem);

    const GemmJob job = (blockIdx.z == 0) ? j0 : (blockIdx.z == 1) ? j1 : j2;
    const __nv_bfloat16* __restrict__ Bhi = job.Bhi;
    const __nv_bfloat16* __restrict__ Blo = job.Blo;

    const int tid  = threadIdx.x;
    const int wid  = tid >> 5;
    const int lane = tid & 31;
    const int wm   = wid >> 2;
    const int wn   = wid & 3;
    const int m0   = blockIdx.y * 128;
    const int n0   = blockIdx.x * 256;

    auto load_stage = [&](int k0, int buf) {
        const uint32_t bo = sb + buf * BUF_STRIDE;
#pragma unroll
        for (int j = 0; j < 8; j++) {
            const int c  = tid + j * 256;
            const int p  = c >> 10;
            const int r  = (c >> 3) & 127;
            const int ch = c & 7;
            const uint32_t dst = bo + p * 16384 + (r << 7) + ((ch ^ (r & 7)) << 4);
            const __nv_bfloat16* src = (p ? Alo : Ahi)
                + (size_t)(m0 + r) * DIMV + k0 + ch * 8;
            CP_ASYNC16(dst, src);
        }
#pragma unroll
        for (int j = 0; j < 16; j++) {
            const int c  = tid + j * 256;
            const int p  = c >> 11;
            const int r  = (c >> 3) & 255;
            const int ch = c & 7;
            const uint32_t dst = bo + 32768 + p * 32768 + (r << 7) + ((ch ^ (r & 7)) << 4);
            const __nv_bfloat16* src = (p ? Blo : Bhi)
                + (size_t)(n0 + r) * DIMV + k0 + ch * 8;
            CP_ASYNC16(dst, src);
        }
    };

    float acc[4][8][4];
#pragma unroll
    for (int i = 0; i < 4; i++)
#pragma unroll
        for (int j = 0; j < 8; j++)
#pragma unroll
            for (int t = 0; t < 4; t++) acc[i][j][t] = 0.f;

    const int a_row = wm * 64 + (lane & 15);
    const int a_chx = lane >> 4;
    const int b_row = wn * 64 + ((lane >> 4) << 3) + (lane & 7);
    const int b_chx = (lane >> 3) & 1;

    load_stage(0, 0);
    CP_COMMIT();

    for (int s = 0; s < 32; s++) {
        const int buf = s & 1;
        if (s + 1 < 32) { load_stage((s + 1) * 64, buf ^ 1); CP_COMMIT(); CP_WAIT1(); }
        else            { CP_WAIT0(); }
        __syncthreads();

        const uint32_t aH = sb + buf * BUF_STRIDE;
        const uint32_t aL = aH + 16384;
        const uint32_t bH = aH + 32768;
        const uint32_t bL = bH + 32768;

#pragma unroll
        for (int kk8 = 0; kk8 < 4; kk8++) {
            uint32_t ah[4][4], al[4][4], bh[8][2], bl[8][2];
            const int ach = kk8 * 2 + a_chx;
#pragma unroll
            for (int i = 0; i < 4; i++) {
                const int r = a_row + i * 16;
                const uint32_t ad = (r << 7) + ((ach ^ (r & 7)) << 4);
                ldsm4(ah[i], aH + ad);
                ldsm4(al[i], aL + ad);
            }
            const int bch = kk8 * 2 + b_chx;
#pragma unroll
            for (int jj = 0; jj < 4; jj++) {
                const int r = b_row + jj * 16;
                const uint32_t bd = (r << 7) + ((bch ^ (r & 7)) << 4);
                uint32_t t[4];
                ldsm4(t, bH + bd);
                bh[2*jj][0] = t[0];   bh[2*jj][1] = t[1];
                bh[2*jj+1][0] = t[2]; bh[2*jj+1][1] = t[3];
                ldsm4(t, bL + bd);
                bl[2*jj][0] = t[0];   bl[2*jj][1] = t[1];
                bl[2*jj+1][0] = t[2]; bl[2*jj+1][1] = t[3];
            }
#pragma unroll
            for (int i = 0; i < 4; i++)
#pragma unroll
                for (int j = 0; j < 8; j++) {
                    mma16816(acc[i][j], ah[i], bh[j]);
                    mma16816(acc[i][j], ah[i], bl[j]);
                    mma16816(acc[i][j], al[i], bh[j]);
                }
        }
        __syncthreads();
    }

    const int mw = m0 + wm * 64;
    const int nw = n0 + wn * 64;
    const int ml = lane >> 2;
    const int nl = (lane & 3) * 2;
    if (job.C != nullptr) {
        float* __restrict__ C = job.C;
        const float* __restrict__ bias = job.bias;
#pragma unroll
        for (int j = 0; j < 8; j++) {
            const int n = nw + j * 8 + nl;
            const float b0 = bias[n], b1 = bias[n + 1];
#pragma unroll
            for (int i = 0; i < 4; i++) {
                const int m = mw + i * 16 + ml;
                *(float2*)&C[(size_t)m * DIMV + n] =
                    make_float2(acc[i][j][0] + b0, acc[i][j][1] + b1);
                *(float2*)&C[(size_t)(m + 8) * DIMV + n] =
                    make_float2(acc[i][j][2] + b0, acc[i][j][3] + b1);
            }
        }
    } else {
        __nv_bfloat16* __restrict__ Chi = job.Chi;
        __nv_bfloat16* __restrict__ Clo = job.Clo;
        const float* __restrict__ bias = job.bias;
#pragma unroll
        for (int j = 0; j < 8; j++) {
            const int n = nw + j * 8 + nl;
            const float b0 = bias[n], b1 = bias[n + 1];
#pragma unroll
            for (int i = 0; i < 4; i++) {
                const int m = mw + i * 16 + ml;
                uint32_t h, l;
                psplit(acc[i][j][0] + b0, acc[i][j][1] + b1, h, l);
                *(uint32_t*)&Chi[(size_t)m * DIMV + n] = h;
                *(uint32_t*)&Clo[(size_t)m * DIMV + n] = l;
                psplit(acc[i][j][2] + b0, acc[i][j][3] + b1, h, l);
                *(uint32_t*)&Chi[(size_t)(m + 8) * DIMV + n] = h;
                *(uint32_t*)&Clo[(size_t)(m + 8) * DIMV + n] = l;
            }
        }
    }
}

// ---------------------------------------------------------------------------
// Fused RMSNorm + RoPE + history-key scaling; writes bf16 hi/lo planes.
// ---------------------------------------------------------------------------
__global__ __launch_bounds__(256)
void normrope_kernel(const float* __restrict__ q, const float* __restrict__ k,
                     const float* __restrict__ rot,
                     const float* __restrict__ wq, const float* __restrict__ wk,
                     const float* __restrict__ hks, const int* __restrict__ oclp,
                     __nv_bfloat16* __restrict__ qhi, __nv_bfloat16* __restrict__ qlo,
                     __nv_bfloat16* __restrict__ khi, __nv_bfloat16* __restrict__ klo)
{
    const int r   = blockIdx.x;
    const int s   = r & (SEQ - 1);
    const int tid = threadIdx.x;
    const float* qrow = q + (size_t)r * DIMV;
    const float* krow = k + (size_t)r * DIMV;
    const int base = tid * 8;

    float qa[8], ka[8];
    {
        float4 t0 = *(const float4*)(qrow + base);
        float4 t1 = *(const float4*)(qrow + base + 4);
        qa[0]=t0.x; qa[1]=t0.y; qa[2]=t0.z; qa[3]=t0.w;
        qa[4]=t1.x; qa[5]=t1.y; qa[6]=t1.z; qa[7]=t1.w;
        float4 u0 = *(const float4*)(krow + base);
        float4 u1 = *(const float4*)(krow + base + 4);
        ka[0]=u0.x; ka[1]=u0.y; ka[2]=u0.z; ka[3]=u0.w;
        ka[4]=u1.x; ka[5]=u1.y; ka[6]=u1.z; ka[7]=u1.w;
    }

    float sq = 0.f, sk = 0.f;
#pragma unroll
    for (int i = 0; i < 8; i++) { sq = fmaf(qa[i], qa[i], sq); sk = fmaf(ka[i], ka[i], sk); }

    __shared__ float2 red[256];
    red[tid] = make_float2(sq, sk);
    __syncthreads();
#pragma unroll
    for (int off = 128; off > 0; off >>= 1) {
        if (tid < off) {
            red[tid].x += red[tid + off].x;
            red[tid].y += red[tid + off].y;
        }
        __syncthreads();
    }
    const float rq = rsqrtf(red[0].x * (1.f / DIMV) + EPSV);
    const float rk = rsqrtf(red[0].y * (1.f / DIMV) + EPSV);

    const int  hist    = SEQ - oclp[0];
    const bool is_hist = (s < hist);
    const float* rrow  = rot + (size_t)s * (2 * DHEAD);

    uint32_t qh[4], ql[4], kh[4], kl[4];
#pragma unroll
    for (int t = 0; t < 4; t++) {
        const int p = (base >> 1) + t;
        const int h = p >> 6;
        const int i = p & 63;
        const float c  = rrow[2*i];
        const float si = rrow[DHEAD + 2*i + 1];
        const int n = base + 2*t;
        float q1 = qa[2*t]     * rq * wq[n];
        float q2 = qa[2*t + 1] * rq * wq[n + 1];
        psplit(q1*c - q2*si, q1*si + q2*c, qh[t], ql[t]);
        float k1 = ka[2*t]     * rk * wk[n];
        float k2 = ka[2*t + 1] * rk * wk[n + 1];
        float ke  = k1*c - k2*si;
        float kod = k1*si + k2*c;
        if (is_hist) {
            const float sc = 1.f + 9.f / (1.f + __expf(-hks[h]));
            ke *= sc; kod *= sc;
        }
        psplit(ke, kod, kh[t], kl[t]);
    }
    *(uint4*)(qhi + (size_t)r * DIMV + base) = make_uint4(qh[0], qh[1], qh[2], qh[3]);
    *(uint4*)(qlo + (size_t)r * DIMV + base) = make_uint4(ql[0], ql[1], ql[2], ql[3]);
    *(uint4*)(khi + (size_t)r * DIMV + base) = make_uint4(kh[0], kh[1], kh[2], kh[3]);
    *(uint4*)(klo + (size_t)r * DIMV + base) = make_uint4(kl[0], kl[1], kl[2], kl[3]);
}

// ---------------------------------------------------------------------------
// Tensor-core flash attention, bf16 3-term (R9/R13-verified shape).
// ---------------------------------------------------------------------------
#define FATT_SMEM 196608
#define FCL2 (0.08838834764831845f * 1.4426950408889634f)

__global__ __launch_bounds__(256, 1)
void flashmma_kernel(const __nv_bfloat16* __restrict__ Qhi, const __nv_bfloat16* __restrict__ Qlo,
                     const __nv_bfloat16* __restrict__ Khi, const __nv_bfloat16* __restrict__ Klo,
                     const __nv_bfloat16* __restrict__ Vhi, const __nv_bfloat16* __restrict__ Vlo,
                     __nv_bfloat16* __restrict__ Ohi, __nv_bfloat16* __restrict__ Olo)
{
    extern __shared__ __align__(1024) char smem[];
    const uint32_t sb   = smem_u32(smem);
    const int tid = threadIdx.x, wid = tid >> 5, lane = tid & 31;
    const int bh = blockIdx.y, b = bh >> 4, h = bh & 15;
    const int q0 = blockIdx.x * 128;
    const size_t rowbase = (size_t)b * SEQ;
    const int hoff = h * DHEAD;

    const uint32_t smQh = sb;
    const uint32_t smQl = sb + 32768;
    const uint32_t smKV = sb + 65536;

#pragma unroll
    for (int j = 0; j < 16; j++) {
        const int c = tid + j * 256;
        const int p = c >> 11, r = (c >> 4) & 127, ch = c & 15;
        const uint32_t dst = (p ? smQl : smQh) + SWZ(r, ch);
        const __nv_bfloat16* src = (p ? Qlo : Qhi)
            + (rowbase + q0 + r) * DIMV + hoff + ch * 8;
        CP_ASYNC16(dst, src);
    }
    auto load_kv = [&](int kv0, int buf) {
        const uint32_t bo = smKV + buf * 65536;
#pragma unroll
        for (int j = 0; j < 16; j++) {
            const int c = tid + j * 256;
            const int p = c >> 10, r = (c >> 4) & 63, ch = c & 15;
            const __nv_bfloat16* pl = (p == 0) ? Khi : (p == 1) ? Klo : (p == 2) ? Vhi : Vlo;
            const uint32_t dst = bo + p * 16384 + SWZ(r, ch);
            CP_ASYNC16(dst, pl + (rowbase + kv0 + r) * DIMV + hoff + ch * 8);
        }
    };
    load_kv(0, 0);
    CP_COMMIT();

    float co[16][4];
#pragma unroll
    for (int j = 0; j < 16; j++)
#pragma unroll
        for (int t = 0; t < 4; t++) co[j][t] = 0.f;
    float m0p = -1e30f, m1p = -1e30f, l0 = 0.f, l1 = 0.f;

    const int a_rl  = wid * 16 + (lane & 15);
    const int a_chx = lane >> 4;
    const int b_rl  = ((lane >> 4) << 3) + (lane & 7);
    const int b_chx = (lane >> 3) & 1;
    const int v_rl  = lane & 15;
    const int v_chx = lane >> 4;

    for (int s = 0; s < 32; s++) {
        const int buf = s & 1;
        if (s + 1 < 32) { load_kv((s + 1) * 64, buf ^ 1); CP_COMMIT(); CP_WAIT1(); }
        else            { CP_WAIT0(); }
        __syncthreads();

        const uint32_t Kh = smKV + buf * 65536;
        const uint32_t Kl = Kh + 16384;
        const uint32_t Vh = Kh + 32768;
        const uint32_t Vl = Kh + 49152;

        float cs[8][4];
#pragma unroll
        for (int j = 0; j < 8; j++)
#pragma unroll
            for (int t = 0; t < 4; t++) cs[j][t] = 0.f;

#pragma unroll
        for (int kk = 0; kk < 8; kk++) {
            uint32_t qh[4], ql[4], kh[8][2], kl[8][2];
            const uint32_t qa = SWZ(a_rl, 2 * kk + a_chx);
            ldsm4(qh, smQh + qa);
            ldsm4(ql, smQl + qa);
#pragma unroll
            for (int jj = 0; jj < 4; jj++) {
                const uint32_t ka = SWZ(16 * jj + b_rl, 2 * kk + b_chx);
                uint32_t t[4];
                ldsm4(t, Kh + ka);
                kh[2*jj][0] = t[0];   kh[2*jj][1] = t[1];
                kh[2*jj+1][0] = t[2]; kh[2*jj+1][1] = t[3];
                ldsm4(t, Kl + ka);
                kl[2*jj][0] = t[0];   kl[2*jj][1] = t[1];
                kl[2*jj+1][0] = t[2]; kl[2*jj+1][1] = t[3];
            }
#pragma unroll
            for (int j = 0; j < 8; j++) {
                mma16816(cs[j], qh, kh[j]);
                mma16816(cs[j], qh, kl[j]);
                mma16816(cs[j], ql, kh[j]);
            }
        }

        float mx0 = -1e30f, mx1 = -1e30f;
#pragma unroll
        for (int j = 0; j < 8; j++) {
            mx0 = fmaxf(mx0, fmaxf(cs[j][0], cs[j][1]));
            mx1 = fmaxf(mx1, fmaxf(cs[j][2], cs[j][3]));
        }
        mx0 = fmaxf(mx0, __shfl_xor_sync(0xffffffffu, mx0, 1));
        mx0 = fmaxf(mx0, __shfl_xor_sync(0xffffffffu, mx0, 2));
        mx1 = fmaxf(mx1, __shfl_xor_sync(0xffffffffu, mx1, 1));
        mx1 = fmaxf(mx1, __shfl_xor_sync(0xffffffffu, mx1, 2));
        const float mn0 = fmaxf(m0p, mx0);
        const float mn1 = fmaxf(m1p, mx1);
        float s0 = 0.f, s1 = 0.f;
#pragma unroll
        for (int j = 0; j < 8; j++) {
            cs[j][0] = exp2f((cs[j][0] - mn0) * FCL2); s0 += cs[j][0];
            cs[j][1] = exp2f((cs[j][1] - mn0) * FCL2); s0 += cs[j][1];
            cs[j][2] = exp2f((cs[j][2] - mn1) * FCL2); s1 += cs[j][2];
            cs[j][3] = exp2f((cs[j][3] - mn1) * FCL2); s1 += cs[j][3];
        }
        s0 += __shfl_xor_sync(0xffffffffu, s0, 1);
        s0 += __shfl_xor_sync(0xffffffffu, s0, 2);
        s1 += __shfl_xor_sync(0xffffffffu, s1, 1);
        s1 += __shfl_xor_sync(0xffffffffu, s1, 2);
        const float al0 = exp2f((m0p - mn0) * FCL2);
        const float al1 = exp2f((m1p - mn1) * FCL2);
        l0 = l0 * al0 + s0;  l1 = l1 * al1 + s1;
        m0p = mn0;  m1p = mn1;
#pragma unroll
        for (int j = 0; j < 16; j++) {
            co[j][0] *= al0; co[j][1] *= al0;
            co[j][2] *= al1; co[j][3] *= al1;
        }

#pragma unroll
        for (int t = 0; t < 4; t++) {
            uint32_t ph[4], pl4[4];
            psplit(cs[2*t][0],   cs[2*t][1],   ph[0], pl4[0]);
            psplit(cs[2*t][2],   cs[2*t][3],   ph[1], pl4[1]);
            psplit(cs[2*t+1][0], cs[2*t+1][1], ph[2], pl4[2]);
            psplit(cs[2*t+1][2], cs[2*t+1][3], ph[3], pl4[3]);
#pragma unroll
            for (int jp = 0; jp < 8; jp++) {
                const uint32_t va = SWZ(16 * t + v_rl, 2 * jp + v_chx);
                uint32_t th[4], tl[4];
                ldsm4t(th, Vh + va);
                ldsm4t(tl, Vl + va);
                mma16816(co[2*jp],   ph,  th);
                mma16816(co[2*jp+1], ph,  th + 2);
                mma16816(co[2*jp],   ph,  tl);
                mma16816(co[2*jp+1], ph,  tl + 2);
                mma16816(co[2*jp],   pl4, th);
                mma16816(co[2*jp+1], pl4, th + 2);
            }
        }
        __syncthreads();
    }

    const float i0 = 1.f / l0, i1 = 1.f / l1;
    const size_t r0 = rowbase + q0 + wid * 16 + (lane >> 2);
    const size_t r1 = r0 + 8;
    const int    cb = hoff + 2 * (lane & 3);
#pragma unroll
    for (int j = 0; j < 16; j++) {
        uint32_t hh, ll;
        psplit(co[j][0] * i0, co[j][1] * i0, hh, ll);
        *(uint32_t*)(Ohi + r0 * DIMV + cb + 8 * j) = hh;
        *(uint32_t*)(Olo + r0 * DIMV + cb + 8 * j) = ll;
        psplit(co[j][2] * i1, co[j][3] * i1, hh, ll);
        *(uint32_t*)(Ohi + r1 * DIMV + cb + 8 * j) = hh;
        *(uint32_t*)(Olo + r1 * DIMV + cb + 8 * j) = ll;
    }
}

// ---------------------------------------------------------------------------
extern "C" void kernel_launch(void* const* d_in, const int* in_sizes, int n_in,
                              void* d_out, int out_size)
{
    const float* hs  = (const float*)d_in[0];
    const float* rot = (const float*)d_in[1];
    const float* Wq  = (const float*)d_in[2];
    const float* bq  = (const float*)d_in[3];
    const float* Wk  = (const float*)d_in[4];
    const float* bk  = (const float*)d_in[5];
    const float* Wv  = (const float*)d_in[6];
    const float* bv  = (const float*)d_in[7];
    const float* nqw = (const float*)d_in[8];
    const float* nkw = (const float*)d_in[9];
    const float* hks = (const float*)d_in[10];
    const float* Wo  = (const float*)d_in[11];
    const float* bo  = (const float*)d_in[12];
    const int*   ocl = (const int*)d_in[13];
    float* out = (float*)d_out;

    float *qp, *kp, *ap;
    cudaGetSymbolAddress((void**)&qp, g_q);
    cudaGetSymbolAddress((void**)&kp, g_k);
    cudaGetSymbolAddress((void**)&ap, g_attn);

    __nv_bfloat16 *ahi, *alo, *khi, *klo, *vhi, *vlo;
    __nv_bfloat16 *wqh, *wql, *wkh, *wkl, *wvh, *wvl, *woh, *wol;
    cudaGetSymbolAddress((void**)&ahi, g_ahi);
    cudaGetSymbolAddress((void**)&alo, g_alo);
    cudaGetSymbolAddress((void**)&khi, g_khi);
    cudaGetSymbolAddress((void**)&klo, g_klo);
    cudaGetSymbolAddress((void**)&vhi, g_vhi);
    cudaGetSymbolAddress((void**)&vlo, g_vlo);
    cudaGetSymbolAddress((void**)&wqh, g_wqhi);
    cudaGetSymbolAddress((void**)&wql, g_wqlo);
    cudaGetSymbolAddress((void**)&wkh, g_wkhi);
    cudaGetSymbolAddress((void**)&wkl, g_wklo);
    cudaGetSymbolAddress((void**)&wvh, g_wvhi);
    cudaGetSymbolAddress((void**)&wvl, g_wvlo);
    cudaGetSymbolAddress((void**)&woh, g_wohi);
    cudaGetSymbolAddress((void**)&wol, g_wolo);

    __nv_bfloat16* ohi = (__nv_bfloat16*)ap;
    __nv_bfloat16* olo = ohi + (size_t)MROWS * DIMV;

    const int nAct = MROWS * DIMV;       // 8.4M
    const int nW   = DIMV * DIMV;        // 4.2M

    // all 5 input splits in ONE launch (grid.y = region)
    split5_kernel<<<dim3(nAct / 1024, 5), 256>>>(
        hs, ahi, alo, nAct,
        Wq, wqh, wql, nW,
        Wk, wkh, wkl, nW,
        Wv, wvh, wvl, nW,
        Wo, woh, wol, nW);

    cudaFuncSetAttribute(gemm_mma_kernel,
                         cudaFuncAttributeMaxDynamicSharedMemorySize, GEMM_SMEM);

    // Q, K, V projections in ONE launch (grid.z = job)
    GemmJob jq { wqh, wql, bq, qp, nullptr, nullptr };
    GemmJob jk { wkh, wkl, bk, kp, nullptr, nullptr };
    GemmJob jv { wvh, wvl, bv, nullptr, vhi, vlo };
    gemm_mma_kernel<<<dim3(DIMV / 256, MROWS / 128, 3), 256, GEMM_SMEM>>>(
        ahi, alo, jq, jk, jv);

    normrope_kernel<<<MROWS, 256>>>(qp, kp, rot, nqw, nkw, hks, ocl,
                                    ahi, alo, khi, klo);

    cudaFuncSetAttribute(flashmma_kernel,
                         cudaFuncAttributeMaxDynamicSharedMemorySize, FATT_SMEM);
    flashmma_kernel<<<dim3(SEQ / 128, BATCH * HEADS), 256, FATT_SMEM>>>(
        ahi, alo, khi, klo, vhi, vlo, ohi, olo);

    GemmJob jo { woh, wol, bo, out, nullptr, nullptr };
    gemm_mma_kernel<<<dim3(DIMV / 256, MROWS / 128, 1), 256, GEMM_SMEM>>>(
        ohi, olo, jo, jo, jo);
}